// round 1
// baseline (speedup 1.0000x reference)
#include <cuda_runtime.h>
#include <cstdint>

#define NBATCH 8
#define NTOT   32768
#define KDIM   128
#define CHUNKS 37
#define ROWS_PER_CHUNK 888   // 37*888 = 32856 >= 32768 (tail zero-filled)
#define KK 8                 // rows staged per pipeline step
#define NSTEPS (ROWS_PER_CHUNK / KK)   // 111
#define JACOBI_ITERS 24

// Scratch (no cudaMalloc allowed): per-batch gram + rhs accumulators.
__device__ float g_gram[NBATCH][KDIM][KDIM];
__device__ float g_m[NBATCH][KDIM];

// ---------------- helpers ----------------
__device__ __forceinline__ void cp_async16(void* smem, const void* gmem, bool pred) {
    uint32_t s = (uint32_t)__cvta_generic_to_shared(smem);
    int sz = pred ? 16 : 0;
    asm volatile("cp.async.cg.shared.global [%0], [%1], 16, %2;\n"
                 :: "r"(s), "l"(gmem), "r"(sz));
}
__device__ __forceinline__ void cp_async4(void* smem, const void* gmem, bool pred) {
    uint32_t s = (uint32_t)__cvta_generic_to_shared(smem);
    int sz = pred ? 4 : 0;
    asm volatile("cp.async.ca.shared.global [%0], [%1], 4, %2;\n"
                 :: "r"(s), "l"(gmem), "r"(sz));
}
#define CP_COMMIT() asm volatile("cp.async.commit_group;\n" ::: "memory")
#define CP_WAIT0()  asm volatile("cp.async.wait_group 0;\n" ::: "memory")

// pack (x, x) into a 64-bit reg (f32x2 lane-replicated operand)
__device__ __forceinline__ unsigned long long pack2(float x) {
    unsigned long long d;
    asm("mov.b64 %0, {%1, %1};" : "=l"(d) : "f"(x));
    return d;
}
__device__ __forceinline__ float2 unpack2(unsigned long long v) {
    float2 r;
    asm("mov.b64 {%0, %1}, %2;" : "=f"(r.x), "=f"(r.y) : "l"(v));
    return r;
}
// packed dual-FMA: acc.{lo,hi} += a.{lo,hi} * b.{lo,hi}
__device__ __forceinline__ void fma2(unsigned long long& acc,
                                     unsigned long long a, unsigned long long b) {
    asm("fma.rn.f32x2 %0, %1, %2, %0;" : "+l"(acc) : "l"(a), "l"(b));
}

// ---------------- kernel 1: zero accumulators ----------------
__global__ void zero_kernel() {
    int idx = blockIdx.x * blockDim.x + threadIdx.x;
    const int NG = NBATCH * KDIM * KDIM;
    if (idx < NG)                    ((float*)g_gram)[idx] = 0.0f;
    else if (idx < NG + NBATCH*KDIM) ((float*)g_m)[idx - NG] = 0.0f;
}

// ---------------- kernel 2: batched gram + rhs ----------------
// Grid: (CHUNKS, 4 batch-pairs). Block: 256 threads (16x16), each thread owns
// an 8x8 output tile for TWO batches (shared mult rows, different mask^2
// weights). Accumulation in packed f32x2 FMAs.
__global__ void __launch_bounds__(256, 1)
gram_kernel(const float* __restrict__ data, const float* __restrict__ mask,
            const float* __restrict__ mult) {
    __shared__ float Ms[2][KK][KDIM];      // raw mult rows
    __shared__ float Sm1[2][KK], Sm2[2][KK];   // raw mask rows (batch pair)
    __shared__ float Sd1[2][KK], Sd2[2][KK];   // raw data rows (batch pair)

    const int chunk = blockIdx.x;
    const int pair  = blockIdx.y;
    const int b1 = pair * 2, b2 = pair * 2 + 1;
    const int tid = threadIdx.x;
    const int tx = tid & 15;        // j-tile: columns tx*8 .. tx*8+7
    const int ty = tid >> 4;        // i-tile: rows    ty*8 .. ty*8+7
    const int n0 = chunk * ROWS_PER_CHUNK;

    const float* mask1 = mask + (size_t)b1 * NTOT;
    const float* mask2 = mask + (size_t)b2 * NTOT;
    const float* data1 = data + (size_t)b1 * NTOT;
    const float* data2 = data + (size_t)b2 * NTOT;

    // staging helper (inlined via lambda)
    auto load_stage = [&](int s, int rowbase) {
        int r = tid >> 5;                 // 0..7
        int c = (tid & 31) * 4;           // 0..124
        int row = rowbase + r;
        bool p = row < NTOT;
        int rc = row < NTOT ? row : (NTOT - 1);
        cp_async16(&Ms[s][r][c], mult + (size_t)rc * KDIM + c, p);
        if (tid < 32) {
            int rr = tid & 7;
            int rown = rowbase + rr;
            bool pp = rown < NTOT;
            int rcl = rown < NTOT ? rown : (NTOT - 1);
            if (tid < 8)       cp_async4(&Sm1[s][rr], mask1 + rcl, pp);
            else if (tid < 16) cp_async4(&Sm2[s][rr], mask2 + rcl, pp);
            else if (tid < 24) cp_async4(&Sd1[s][rr], data1 + rcl, pp);
            else               cp_async4(&Sd2[s][rr], data2 + rcl, pp);
        }
        CP_COMMIT();
    };

    unsigned long long acc1[8][4];   // batch b1: 8 rows x 4 column-pairs
    unsigned long long acc2[8][4];   // batch b2
    unsigned long long mloc1[4], mloc2[4];   // rhs partials (ty==0 threads)
    #pragma unroll
    for (int i = 0; i < 8; ++i)
        #pragma unroll
        for (int j = 0; j < 4; ++j) { acc1[i][j] = 0ull; acc2[i][j] = 0ull; }
    #pragma unroll
    for (int j = 0; j < 4; ++j) { mloc1[j] = 0ull; mloc2[j] = 0ull; }

    load_stage(0, n0);
    CP_WAIT0();
    __syncthreads();

    for (int step = 0; step < NSTEPS; ++step) {
        int s = step & 1;
        if (step + 1 < NSTEPS) load_stage(s ^ 1, n0 + (step + 1) * KK);

        #pragma unroll
        for (int k = 0; k < KK; ++k) {
            float4 a0 = *(const float4*)&Ms[s][k][ty * 8];
            float4 a1 = *(const float4*)&Ms[s][k][ty * 8 + 4];
            unsigned long long bd[4];
            #pragma unroll
            for (int j = 0; j < 4; ++j)
                bd[j] = *(const unsigned long long*)&Ms[s][k][tx * 8 + j * 2];

            float mk1 = Sm1[s][k], mk2 = Sm2[s][k];
            float w1 = mk1 * mk1, w2 = mk2 * mk2;

            float av[8] = {a0.x, a0.y, a0.z, a0.w, a1.x, a1.y, a1.z, a1.w};
            #pragma unroll
            for (int ii = 0; ii < 8; ++ii) {
                unsigned long long aw1 = pack2(av[ii] * w1);
                unsigned long long aw2 = pack2(av[ii] * w2);
                #pragma unroll
                for (int j = 0; j < 4; ++j) {
                    fma2(acc1[ii][j], aw1, bd[j]);
                    fma2(acc2[ii][j], aw2, bd[j]);
                }
            }
            if (ty == 0) {
                unsigned long long d1p = pack2(mk1 * Sd1[s][k]);
                unsigned long long d2p = pack2(mk2 * Sd2[s][k]);
                #pragma unroll
                for (int j = 0; j < 4; ++j) {
                    fma2(mloc1[j], d1p, bd[j]);
                    fma2(mloc2[j], d2p, bd[j]);
                }
            }
        }
        CP_WAIT0();
        __syncthreads();
    }

    // combine partial grams (scalar RED; candidate for v4 red next round)
    #pragma unroll
    for (int ii = 0; ii < 8; ++ii) {
        int gi = ty * 8 + ii;
        #pragma unroll
        for (int j = 0; j < 4; ++j) {
            float2 v1 = unpack2(acc1[ii][j]);
            float2 v2 = unpack2(acc2[ii][j]);
            int gj = tx * 8 + j * 2;
            atomicAdd(&g_gram[b1][gi][gj],     v1.x);
            atomicAdd(&g_gram[b1][gi][gj + 1], v1.y);
            atomicAdd(&g_gram[b2][gi][gj],     v2.x);
            atomicAdd(&g_gram[b2][gi][gj + 1], v2.y);
        }
    }
    if (ty == 0) {
        #pragma unroll
        for (int j = 0; j < 4; ++j) {
            float2 v1 = unpack2(mloc1[j]);
            float2 v2 = unpack2(mloc2[j]);
            int gj = tx * 8 + j * 2;
            atomicAdd(&g_m[b1][gj],     v1.x);
            atomicAdd(&g_m[b1][gj + 1], v1.y);
            atomicAdd(&g_m[b2][gj],     v2.x);
            atomicAdd(&g_m[b2][gj + 1], v2.y);
        }
    }
}

// ---------------- kernel 3: Jacobi solve (G + sigma^2 I) x = m ----------------
// G is ~27*I + small noise (spectral radius of Jacobi iteration ~0.17), so a
// fixed 24 sweeps reach fp32 machine precision. One block per batch.
__global__ void solve_kernel(const float* __restrict__ sigma_sq,
                             float* __restrict__ out) {
    __shared__ float Gs[KDIM][KDIM + 1];
    __shared__ float xa[KDIM], xb[KDIM], mv[KDIM];
    const int b = blockIdx.x;
    const int tid = threadIdx.x;   // 128 threads

    for (int idx = tid; idx < KDIM * KDIM; idx += KDIM)
        Gs[idx >> 7][idx & 127] = g_gram[b][idx >> 7][idx & 127];
    mv[tid] = g_m[b][tid];
    __syncthreads();

    float sig = sigma_sq[0];
    Gs[tid][tid] += sig;
    __syncthreads();

    float di = 1.0f / Gs[tid][tid];
    xa[tid] = mv[tid] * di;
    __syncthreads();

    for (int it = 0; it < JACOBI_ITERS; ++it) {
        const float* xr = (it & 1) ? xb : xa;
        float*       xw = (it & 1) ? xa : xb;
        float r = mv[tid];
        #pragma unroll 16
        for (int j = 0; j < KDIM; ++j) r -= Gs[tid][j] * xr[j];
        xw[tid] = xr[tid] + di * r;
        __syncthreads();
    }
    // JACOBI_ITERS even -> final result in xa
    out[b * KDIM + tid] = xa[tid];
}

// ---------------- launch ----------------
extern "C" void kernel_launch(void* const* d_in, const int* in_sizes, int n_in,
                              void* d_out, int out_size) {
    const float* data  = (const float*)d_in[0];
    const float* mask  = (const float*)d_in[1];
    const float* mult  = (const float*)d_in[2];
    const float* sigma = (const float*)d_in[3];
    float* out = (float*)d_out;

    const int total = NBATCH * KDIM * KDIM + NBATCH * KDIM;   // 132096
    zero_kernel<<<(total + 255) / 256, 256>>>();

    dim3 grid(CHUNKS, NBATCH / 2);
    gram_kernel<<<grid, 256>>>(data, mask, mult);

    solve_kernel<<<NBATCH, KDIM>>>(sigma, out);
}

// round 3
// speedup vs baseline: 2.3310x; 2.3310x over previous
#include <cuda_runtime.h>
#include <cstdint>

#define NBATCH 8
#define NTOT   32768
#define KDIM   128
#define NCH    18
#define TILE_N 64
#define CHUNK_TILES 29          // 17*29 + 19 = 512 tiles total
#define JACOBI_ITERS 24
#define THREADS 256

// ---------------- global scratch (no cudaMalloc allowed) ----------------
// g_scr[acc][chunk][b][i][j] : acc 0 = H^T H, acc 1 = H^T L   (row-major D[i][j])
__device__ float g_scr[2][NCH][NBATCH][KDIM][KDIM];
__device__ float g_msr[NCH][NBATCH][KDIM];
__device__ float g_sa[2][NBATCH][KDIM][KDIM];
__device__ float g_mred[NBATCH][KDIM];

// ---------------- smem layout for gram kernel (dynamic) ----------------
#define ROWB   272                     // bytes per H/L row: 128 bf16 + 8 pad = 272B (17*16)
#define SM_STAGE 0                     // [2][64][128] f32 = 65536
#define SM_H     65536                 // 64 rows * 272B  = 17408
#define SM_L     82944                 // 17408
#define SM_MSK   100352                // [2][64] f32
#define SM_DAT   100864                // [2][64] f32
#define SM_MRED  101376                // [128] f32
#define SMEM_TOTAL 101888

// ---------------- helpers ----------------
__device__ __forceinline__ uint32_t smem_u32(const void* p) {
    uint32_t a;
    asm("{ .reg .u64 t; cvta.to.shared.u64 t, %1; cvt.u32.u64 %0, t; }"
        : "=r"(a) : "l"(p));
    return a;
}
__device__ __forceinline__ void cp16(void* s, const void* g) {
    uint32_t a = smem_u32(s);
    asm volatile("cp.async.cg.shared.global [%0], [%1], 16;" :: "r"(a), "l"(g));
}
#define CP_COMMIT() asm volatile("cp.async.commit_group;" ::: "memory")
#define CP_WAIT(n)  asm volatile("cp.async.wait_group %0;" :: "n"(n) : "memory")

__device__ __forceinline__ void ldsm4t(uint32_t* r, uint32_t addr) {
    asm volatile("ldmatrix.sync.aligned.m8n8.x4.trans.shared.b16 {%0,%1,%2,%3}, [%4];"
                 : "=r"(r[0]), "=r"(r[1]), "=r"(r[2]), "=r"(r[3]) : "r"(addr));
}
__device__ __forceinline__ void mma_bf16(float* d, const uint32_t* a, const uint32_t* b) {
    asm volatile(
        "mma.sync.aligned.m16n8k16.row.col.f32.bf16.bf16.f32 "
        "{%0,%1,%2,%3}, {%4,%5,%6,%7}, {%8,%9}, {%0,%1,%2,%3};"
        : "+f"(d[0]), "+f"(d[1]), "+f"(d[2]), "+f"(d[3])
        : "r"(a[0]), "r"(a[1]), "r"(a[2]), "r"(a[3]), "r"(b[0]), "r"(b[1]));
}

// ---------------- kernel 1: split-K gram via mma.sync bf16 hi/lo ----------------
__global__ void __launch_bounds__(THREADS, 1)
gram_kernel(const float* __restrict__ data, const float* __restrict__ mask,
            const float* __restrict__ mult) {
    extern __shared__ char smem[];
    const uint32_t smb = smem_u32(smem);
    const int tid = threadIdx.x;
    const int wid = tid >> 5;
    const int lane = tid & 31;
    const int chunk = blockIdx.x;
    const int b = blockIdx.y;
    const int n_start = chunk * (CHUNK_TILES * TILE_N);
    const int T = min(CHUNK_TILES, (NTOT - n_start) / TILE_N);

    float* stage = (float*)(smem + SM_STAGE);
    float* msk   = (float*)(smem + SM_MSK);
    float* dat   = (float*)(smem + SM_DAT);
    float* mred  = (float*)(smem + SM_MRED);
    const float* maskb = mask + (size_t)b * NTOT;
    const float* datab = data + (size_t)b * NTOT;

    if (tid < 128) mred[tid] = 0.f;

    auto prefetch = [&](int tt) {
        const int sb = tt & 1;
        const float* src = mult + (size_t)(n_start + tt * TILE_N) * KDIM;
        float* dst = stage + sb * (TILE_N * KDIM);
        #pragma unroll
        for (int s = 0; s < 8; ++s) {
            const int seg = tid + s * THREADS;         // 0..2047 16B segments
            cp16(dst + seg * 4, src + seg * 4);
        }
        if (tid < 16)      cp16(&msk[sb * 64 + tid * 4],        maskb + n_start + tt * 64 + tid * 4);
        else if (tid < 32) cp16(&dat[sb * 64 + (tid - 16) * 4], datab + n_start + tt * 64 + (tid - 16) * 4);
        CP_COMMIT();
    };

    prefetch(0);

    // conversion mapping: thread owns k-pair k2, 16 n-rows
    const int k2 = (tid & 63) * 2;
    const int ng = tid >> 6;                 // 0..3
    float macc0 = 0.f, macc1 = 0.f;

    // MMA warp tiling: 4x2 warp grid, warp tile 32(i) x 64(j)
    const int i0 = (wid >> 1) * 32;
    const int j0 = (wid & 1) * 64;
    // ldmatrix lane addressing (byte offsets relative to H/L base, per k-step add ks*16*ROWB)
    const int grp = lane >> 3, r = lane & 7;
    // A: g0:(kk0-7,i0) g1:(kk0-7,i0+8) g2:(kk8-15,i0) g3:(kk8-15,i0+8)
    const uint32_t a_off = (uint32_t)(((grp & 2) ? 8 : 0) + r) * ROWB + (uint32_t)((grp & 1) ? 8 : 0) * 2;
    // B: g0:(kk0-7,j) g1:(kk8-15,j) g2:(kk0-7,j+8) g3:(kk8-15,j+8)
    const uint32_t b_off = (uint32_t)(((grp & 1) ? 8 : 0) + r) * ROWB + (uint32_t)((grp & 2) ? 8 : 0) * 2;

    float accHH[2][4][2][4];   // [m-tile][n-group][n8-tile][4 regs]
    float accHL[2][4][2][4];
    #pragma unroll
    for (int mt = 0; mt < 2; ++mt)
        #pragma unroll
        for (int g = 0; g < 4; ++g)
            #pragma unroll
            for (int nt = 0; nt < 2; ++nt)
                #pragma unroll
                for (int q = 0; q < 4; ++q) { accHH[mt][g][nt][q] = 0.f; accHL[mt][g][nt][q] = 0.f; }

    for (int t = 0; t < T; ++t) {
        const int sb = t & 1;
        if (t + 1 < T) { prefetch(t + 1); CP_WAIT(1); }
        else           { CP_WAIT(0); }
        __syncthreads();    // stage[sb] ready for all; H/L free (prev MMA done)

        // ---- convert fp32 -> H (bf16) + L (residual bf16), fold rhs ----
        {
            const float* st = stage + sb * (TILE_N * KDIM);
            const float* mk = msk + sb * 64;
            const float* dd = dat + sb * 64;
            char* hp_base = smem + SM_H;
            char* lp_base = smem + SM_L;
            #pragma unroll
            for (int i = 0; i < 16; ++i) {
                const int n = ng * 16 + i;
                const float2 v = *(const float2*)&st[n * KDIM + k2];
                const float w = mk[n], d = dd[n];
                const float x0 = v.x * w, x1 = v.y * w;
                macc0 = fmaf(x0, d, macc0);
                macc1 = fmaf(x1, d, macc1);
                uint32_t hp;
                asm("cvt.rn.bf16x2.f32 %0, %1, %2;" : "=r"(hp) : "f"(x1), "f"(x0));
                const float h0 = __uint_as_float(hp << 16);
                const float h1 = __uint_as_float(hp & 0xffff0000u);
                uint32_t lp;
                asm("cvt.rn.bf16x2.f32 %0, %1, %2;" : "=r"(lp) : "f"(x1 - h1), "f"(x0 - h0));
                *(uint32_t*)(hp_base + n * ROWB + k2 * 2) = hp;
                *(uint32_t*)(lp_base + n * ROWB + k2 * 2) = lp;
            }
        }
        __syncthreads();    // H/L visible to all warps

        // ---- MMAs: 4 k-steps of 16 over the 64 rows ----
        #pragma unroll
        for (int ks = 0; ks < 4; ++ks) {
            const uint32_t kofs = (uint32_t)ks * 16 * ROWB;
            uint32_t afrag[2][4];
            ldsm4t(afrag[0], smb + SM_H + kofs + a_off + (uint32_t)(i0) * 2);
            ldsm4t(afrag[1], smb + SM_H + kofs + a_off + (uint32_t)(i0 + 16) * 2);
            #pragma unroll
            for (int g = 0; g < 4; ++g) {
                const uint32_t cofs = (uint32_t)(j0 + g * 16) * 2;
                uint32_t bh[4], bl[4];
                ldsm4t(bh, smb + SM_H + kofs + b_off + cofs);
                ldsm4t(bl, smb + SM_L + kofs + b_off + cofs);
                #pragma unroll
                for (int mt = 0; mt < 2; ++mt) {
                    mma_bf16(accHH[mt][g][0], afrag[mt], bh + 0);
                    mma_bf16(accHH[mt][g][1], afrag[mt], bh + 2);
                    mma_bf16(accHL[mt][g][0], afrag[mt], bl + 0);
                    mma_bf16(accHL[mt][g][1], afrag[mt], bl + 2);
                }
            }
        }
    }

    // ---- rhs partial reduce (4 contributions per k) ----
    atomicAdd(&mred[k2], macc0);
    atomicAdd(&mred[k2 + 1], macc1);
    __syncthreads();
    if (tid < 128) g_msr[chunk][b][tid] = mred[tid];

    // ---- epilogue: accumulators -> global scratch ----
    const int dg = lane >> 2, dt = (lane & 3) * 2;
    #pragma unroll
    for (int mt = 0; mt < 2; ++mt) {
        #pragma unroll
        for (int g = 0; g < 4; ++g) {
            #pragma unroll
            for (int nt = 0; nt < 2; ++nt) {
                const int i = i0 + mt * 16 + dg;
                const int j = j0 + g * 16 + nt * 8 + dt;
                *(float2*)&g_scr[0][chunk][b][i][j]     = make_float2(accHH[mt][g][nt][0], accHH[mt][g][nt][1]);
                *(float2*)&g_scr[0][chunk][b][i + 8][j] = make_float2(accHH[mt][g][nt][2], accHH[mt][g][nt][3]);
                *(float2*)&g_scr[1][chunk][b][i][j]     = make_float2(accHL[mt][g][nt][0], accHL[mt][g][nt][1]);
                *(float2*)&g_scr[1][chunk][b][i + 8][j] = make_float2(accHL[mt][g][nt][2], accHL[mt][g][nt][3]);
            }
        }
    }
}

// ---------------- kernel 2: reduce split-K partials ----------------
__global__ void reduce_kernel() {
    const int idx = blockIdx.x * 256 + threadIdx.x;
    const int PER = NBATCH * KDIM * KDIM;   // 131072
    if (idx < 2 * PER) {
        const int accid = idx / PER;
        const int rem = idx - accid * PER;
        const float* p = (const float*)g_scr + (size_t)accid * NCH * PER + rem;
        float s = 0.f;
        #pragma unroll
        for (int c = 0; c < NCH; ++c) s += p[(size_t)c * PER];
        ((float*)g_sa)[idx] = s;
    } else if (idx < 2 * PER + NBATCH * KDIM) {
        const int r = idx - 2 * PER;
        const float* p = (const float*)g_msr + r;
        float s = 0.f;
        #pragma unroll
        for (int c = 0; c < NCH; ++c) s += p[c * NBATCH * KDIM];
        ((float*)g_mred)[r] = s;
    }
}

// ---------------- kernel 3: Jacobi solve ----------------
// G[i][j] = HH[i][j] + HL[i][j] + HL[j][i] + sigma^2 * (i==j)
#define SOLVE_SMEM ((128 * 129 + 2 * 128 + 128) * 4)
__global__ void solve_kernel(const float* __restrict__ sigma_sq,
                             float* __restrict__ out) {
    extern __shared__ float ssm[];          // S1[128][129] | xs[2][128] | mv[128]
    float* S1 = ssm;
    float* xs = ssm + 128 * 129;
    float* mv = xs + 2 * 128;
    const int b = blockIdx.x;
    const int tid = threadIdx.x;            // 256
    const int i = tid >> 1;
    const int half = tid & 1;
    const int c0 = half * 64;
    const float sig = sigma_sq[0];

    for (int idx = tid; idx < KDIM * KDIM; idx += THREADS)
        S1[(idx >> 7) * 129 + (idx & 127)] = g_sa[1][b][idx >> 7][idx & 127];
    if (tid < KDIM) mv[tid] = g_mred[b][tid];
    __syncthreads();

    float G[64];
    #pragma unroll 8
    for (int j = 0; j < 64; ++j) {
        const int c = c0 + j;
        float v = g_sa[0][b][i][c] + S1[i * 129 + c] + S1[c * 129 + i];
        if (c == i) v += sig;
        G[j] = v;
    }

    float dval = (half == (i >> 6)) ? G[i - c0] : 0.f;
    dval += __shfl_xor_sync(0xffffffffu, dval, 1);
    const float di = 1.f / dval;
    if (half == 0) xs[i] = mv[i] * di;
    __syncthreads();

    for (int it = 0; it < JACOBI_ITERS; ++it) {
        const float* xr = xs + (it & 1) * 128;
        float* xw = xs + ((it & 1) ^ 1) * 128;
        float s = 0.f;
        #pragma unroll 16
        for (int j = 0; j < 64; ++j) s = fmaf(G[j], xr[c0 + j], s);
        s += __shfl_xor_sync(0xffffffffu, s, 1);
        if (half == 0) xw[i] = xr[i] + di * (mv[i] - s);
        __syncthreads();
    }
    if (half == 0) out[b * KDIM + i] = xs[i];   // even iter count -> buffer 0
}

// ---------------- launch ----------------
extern "C" void kernel_launch(void* const* d_in, const int* in_sizes, int n_in,
                              void* d_out, int out_size) {
    const float* data  = (const float*)d_in[0];
    const float* mask  = (const float*)d_in[1];
    const float* mult  = (const float*)d_in[2];
    const float* sigma = (const float*)d_in[3];
    float* out = (float*)d_out;

    cudaFuncSetAttribute(gram_kernel,
                         cudaFuncAttributeMaxDynamicSharedMemorySize, SMEM_TOTAL);
    cudaFuncSetAttribute(solve_kernel,
                         cudaFuncAttributeMaxDynamicSharedMemorySize, SOLVE_SMEM);

    dim3 grid(NCH, NBATCH);
    gram_kernel<<<grid, THREADS, SMEM_TOTAL>>>(data, mask, mult);

    const int total = 2 * NBATCH * KDIM * KDIM + NBATCH * KDIM;
    reduce_kernel<<<(total + 255) / 256, 256>>>();

    solve_kernel<<<NBATCH, THREADS, SOLVE_SMEM>>>(sigma, out);
}

// round 4
// speedup vs baseline: 3.8943x; 1.6706x over previous
#include <cuda_runtime.h>
#include <cstdint>

#define NBATCH 8
#define NTOT   32768
#define KDIM   128
#define NCH    37
#define TILE_N 64
#define CHUNK_TILES 14          // 37*14 = 518 >= 512 tiles; last chunk has 8
#define JACOBI_ITERS 24
#define THREADS 256

// ---------------- global scratch (no cudaMalloc allowed) ----------------
// g_scr[chunk][b][i][j] : partial C = P^T P (symmetric), fp32
__device__ float g_scr[NCH][NBATCH][KDIM][KDIM];
__device__ float g_msr[NCH][NBATCH][KDIM];
__device__ float g_sa[NBATCH][KDIM][KDIM];
__device__ float g_mred[NBATCH][KDIM];

// ---------------- smem layout for gram kernel (dynamic) ----------------
#define ROWB   272                     // bytes per H row: 128 f16 (256B) + 16 pad
#define SM_STAGE 0                     // [2][64][128] f32 = 65536
#define SM_H     65536                 // 64 * 272 = 17408
#define SM_MSK   82944                 // [2][64] f32
#define SM_DAT   83456                 // [2][64] f32
#define SM_MRED  83968                 // [128] f32
#define SMEM_TOTAL 84480

// ---------------- helpers ----------------
__device__ __forceinline__ uint32_t smem_u32(const void* p) {
    uint32_t a;
    asm("{ .reg .u64 t; cvta.to.shared.u64 t, %1; cvt.u32.u64 %0, t; }"
        : "=r"(a) : "l"(p));
    return a;
}
__device__ __forceinline__ void cp16(void* s, const void* g) {
    uint32_t a = smem_u32(s);
    asm volatile("cp.async.cg.shared.global [%0], [%1], 16;" :: "r"(a), "l"(g));
}
#define CP_COMMIT() asm volatile("cp.async.commit_group;" ::: "memory")
#define CP_WAIT(n)  asm volatile("cp.async.wait_group %0;" :: "n"(n) : "memory")

__device__ __forceinline__ void ldsm4t(uint32_t* r, uint32_t addr) {
    asm volatile("ldmatrix.sync.aligned.m8n8.x4.trans.shared.b16 {%0,%1,%2,%3}, [%4];"
                 : "=r"(r[0]), "=r"(r[1]), "=r"(r[2]), "=r"(r[3]) : "r"(addr));
}
__device__ __forceinline__ void mma_f16(float* d, const uint32_t* a, const uint32_t* b) {
    asm volatile(
        "mma.sync.aligned.m16n8k16.row.col.f32.f16.f16.f32 "
        "{%0,%1,%2,%3}, {%4,%5,%6,%7}, {%8,%9}, {%0,%1,%2,%3};"
        : "+f"(d[0]), "+f"(d[1]), "+f"(d[2]), "+f"(d[3])
        : "r"(a[0]), "r"(a[1]), "r"(a[2]), "r"(a[3]), "r"(b[0]), "r"(b[1]));
}

// ---------------- kernel 1: split-K gram via mma.sync fp16 ----------------
__global__ void __launch_bounds__(THREADS, 2)
gram_kernel(const float* __restrict__ data, const float* __restrict__ mask,
            const float* __restrict__ mult) {
    extern __shared__ char smem[];
    const uint32_t smb = smem_u32(smem);
    const int tid = threadIdx.x;
    const int wid = tid >> 5;
    const int lane = tid & 31;
    const int chunk = blockIdx.x;
    const int b = blockIdx.y;
    const int n_start = chunk * (CHUNK_TILES * TILE_N);
    const int T = min(CHUNK_TILES, (NTOT - n_start) / TILE_N);

    float* stage = (float*)(smem + SM_STAGE);
    float* msk   = (float*)(smem + SM_MSK);
    float* dat   = (float*)(smem + SM_DAT);
    float* mred  = (float*)(smem + SM_MRED);
    const float* maskb = mask + (size_t)b * NTOT;
    const float* datab = data + (size_t)b * NTOT;

    if (tid < 128) mred[tid] = 0.f;

    auto prefetch = [&](int tt) {
        const int sb = tt & 1;
        const float* src = mult + (size_t)(n_start + tt * TILE_N) * KDIM;
        float* dst = stage + sb * (TILE_N * KDIM);
        #pragma unroll
        for (int s = 0; s < 8; ++s) {
            const int seg = tid + s * THREADS;         // 0..2047 16B segments
            cp16(dst + seg * 4, src + seg * 4);
        }
        if (tid < 16)      cp16(&msk[sb * 64 + tid * 4],        maskb + n_start + tt * 64 + tid * 4);
        else if (tid < 32) cp16(&dat[sb * 64 + (tid - 16) * 4], datab + n_start + tt * 64 + (tid - 16) * 4);
        CP_COMMIT();
    };

    prefetch(0);

    // conversion mapping: thread owns k-pair k2, 16 n-rows
    const int k2 = (tid & 63) * 2;
    const int ng = tid >> 6;                 // 0..3
    float macc0 = 0.f, macc1 = 0.f;

    // MMA warp tiling: 4x2 warp grid, warp tile 32(i) x 64(j)
    const int i0 = (wid >> 1) * 32;
    const int j0 = (wid & 1) * 64;
    // ldmatrix lane addressing (validated in round 3)
    const int grp = lane >> 3, r = lane & 7;
    const uint32_t a_off = (uint32_t)(((grp & 2) ? 8 : 0) + r) * ROWB + (uint32_t)((grp & 1) ? 8 : 0) * 2;
    const uint32_t b_off = (uint32_t)(((grp & 1) ? 8 : 0) + r) * ROWB + (uint32_t)((grp & 2) ? 8 : 0) * 2;

    float acc[2][4][2][4];   // [m-tile][n-group][n8-tile][4 regs]
    #pragma unroll
    for (int mt = 0; mt < 2; ++mt)
        #pragma unroll
        for (int g = 0; g < 4; ++g)
            #pragma unroll
            for (int nt = 0; nt < 2; ++nt)
                #pragma unroll
                for (int q = 0; q < 4; ++q) acc[mt][g][nt][q] = 0.f;

    for (int t = 0; t < T; ++t) {
        const int sb = t & 1;
        if (t + 1 < T) { prefetch(t + 1); CP_WAIT(1); }
        else           { CP_WAIT(0); }
        __syncthreads();    // stage[sb] ready; H free (prev MMA done)

        // ---- convert fp32 -> fp16, fold rhs ----
        {
            const float* st = stage + sb * (TILE_N * KDIM);
            const float* mk = msk + sb * 64;
            const float* dd = dat + sb * 64;
            char* hp_base = smem + SM_H;
            #pragma unroll
            for (int i = 0; i < 16; ++i) {
                const int n = ng * 16 + i;
                const float2 v = *(const float2*)&st[n * KDIM + k2];
                const float w = mk[n], d = dd[n];
                const float x0 = v.x * w, x1 = v.y * w;
                macc0 = fmaf(x0, d, macc0);
                macc1 = fmaf(x1, d, macc1);
                uint32_t hp;
                asm("cvt.rn.f16x2.f32 %0, %1, %2;" : "=r"(hp) : "f"(x1), "f"(x0));
                *(uint32_t*)(hp_base + n * ROWB + k2 * 2) = hp;
            }
        }
        __syncthreads();    // H visible to all warps

        // ---- MMAs: 4 k-steps of 16 over the 64 rows ----
        #pragma unroll
        for (int ks = 0; ks < 4; ++ks) {
            const uint32_t kofs = SM_H + (uint32_t)ks * 16 * ROWB;
            uint32_t afrag[2][4];
            ldsm4t(afrag[0], smb + kofs + a_off + (uint32_t)(i0) * 2);
            ldsm4t(afrag[1], smb + kofs + a_off + (uint32_t)(i0 + 16) * 2);
            #pragma unroll
            for (int g = 0; g < 4; ++g) {
                uint32_t bh[4];
                ldsm4t(bh, smb + kofs + b_off + (uint32_t)(j0 + g * 16) * 2);
                #pragma unroll
                for (int mt = 0; mt < 2; ++mt) {
                    mma_f16(acc[mt][g][0], afrag[mt], bh + 0);
                    mma_f16(acc[mt][g][1], afrag[mt], bh + 2);
                }
            }
        }
    }

    // ---- rhs partial reduce ----
    atomicAdd(&mred[k2], macc0);
    atomicAdd(&mred[k2 + 1], macc1);
    __syncthreads();
    if (tid < 128) g_msr[chunk][b][tid] = mred[tid];

    // ---- epilogue: accumulators -> global scratch ----
    const int dg = lane >> 2, dt = (lane & 3) * 2;
    #pragma unroll
    for (int mt = 0; mt < 2; ++mt) {
        #pragma unroll
        for (int g = 0; g < 4; ++g) {
            #pragma unroll
            for (int nt = 0; nt < 2; ++nt) {
                const int i = i0 + mt * 16 + dg;
                const int j = j0 + g * 16 + nt * 8 + dt;
                *(float2*)&g_scr[chunk][b][i][j]     = make_float2(acc[mt][g][nt][0], acc[mt][g][nt][1]);
                *(float2*)&g_scr[chunk][b][i + 8][j] = make_float2(acc[mt][g][nt][2], acc[mt][g][nt][3]);
            }
        }
    }
}

// ---------------- kernel 2: reduce split-K partials ----------------
__global__ void reduce_kernel() {
    const int idx = blockIdx.x * 256 + threadIdx.x;
    const int PER = NBATCH * KDIM * KDIM;   // 131072
    if (idx < PER) {
        const float* p = (const float*)g_scr + idx;
        float s = 0.f;
        #pragma unroll
        for (int c = 0; c < NCH; ++c) s += p[(size_t)c * PER];
        ((float*)g_sa)[idx] = s;
    } else if (idx < PER + NBATCH * KDIM) {
        const int r = idx - PER;
        const float* p = (const float*)g_msr + r;
        float s = 0.f;
        #pragma unroll
        for (int c = 0; c < NCH; ++c) s += p[c * NBATCH * KDIM];
        ((float*)g_mred)[r] = s;
    }
}

// ---------------- kernel 3: Jacobi solve ----------------
// G[i][j] = C[i][j] + sigma^2 * (i==j)   (C symmetric by construction)
__global__ void solve_kernel(const float* __restrict__ sigma_sq,
                             float* __restrict__ out) {
    __shared__ float xs[2][KDIM];
    __shared__ float mv[KDIM];
    const int b = blockIdx.x;
    const int tid = threadIdx.x;            // 256
    const int i = tid >> 1;
    const int half = tid & 1;
    const int c0 = half * 64;
    const float sig = sigma_sq[0];

    float G[64];
    #pragma unroll 8
    for (int j = 0; j < 64; ++j) {
        const int c = c0 + j;
        float v = g_sa[b][i][c];
        if (c == i) v += sig;
        G[j] = v;
    }
    if (tid < KDIM) mv[tid] = g_mred[b][tid];

    float dval = (half == (i >> 6)) ? G[i - c0] : 0.f;
    dval += __shfl_xor_sync(0xffffffffu, dval, 1);
    const float di = 1.f / dval;
    __syncthreads();
    if (half == 0) xs[0][i] = mv[i] * di;
    __syncthreads();

    for (int it = 0; it < JACOBI_ITERS; ++it) {
        const float* xr = xs[it & 1];
        float* xw = xs[(it & 1) ^ 1];
        float s = 0.f;
        #pragma unroll 16
        for (int j = 0; j < 64; ++j) s = fmaf(G[j], xr[c0 + j], s);
        s += __shfl_xor_sync(0xffffffffu, s, 1);
        if (half == 0) xw[i] = xr[i] + di * (mv[i] - s);
        __syncthreads();
    }
    if (half == 0) out[b * KDIM + i] = xs[0][i];   // even iter count -> buffer 0
}

// ---------------- launch ----------------
extern "C" void kernel_launch(void* const* d_in, const int* in_sizes, int n_in,
                              void* d_out, int out_size) {
    const float* data  = (const float*)d_in[0];
    const float* mask  = (const float*)d_in[1];
    const float* mult  = (const float*)d_in[2];
    const float* sigma = (const float*)d_in[3];
    float* out = (float*)d_out;

    cudaFuncSetAttribute(gram_kernel,
                         cudaFuncAttributeMaxDynamicSharedMemorySize, SMEM_TOTAL);

    dim3 grid(NCH, NBATCH);
    gram_kernel<<<grid, THREADS, SMEM_TOTAL>>>(data, mask, mult);

    const int total = NBATCH * KDIM * KDIM + NBATCH * KDIM;
    reduce_kernel<<<(total + 255) / 256, 256>>>();

    solve_kernel<<<NBATCH, THREADS>>>(sigma, out);
}

// round 5
// speedup vs baseline: 4.0408x; 1.0376x over previous
#include <cuda_runtime.h>
#include <cstdint>

#define NBATCH 8
#define NTOT   32768
#define KDIM   128
#define NCH    37
#define TILE_N 64
#define CHUNK_TILES 14          // 37*14*64 = 33152 >= 32768; last chunk has 8 tiles
#define JACOBI_ITERS 24
#define THREADS 256
#define ROWB   272              // bytes per H row: 128 f16 (256B) + 16 pad

// ---------------- global scratch (no cudaMalloc allowed) ----------------
// g_scr[chunk][b][i][j] : partial C = P^T P; lower-left quadrant (i>=64,j<64) never written
__device__ float g_scr[NCH][NBATCH][KDIM][KDIM];
__device__ float g_msr[NCH][NBATCH][KDIM];
__device__ float g_sa[NBATCH][KDIM][KDIM];
__device__ float g_mred[NBATCH][KDIM];

// ---------------- helpers ----------------
__device__ __forceinline__ uint32_t smem_u32(const void* p) {
    uint32_t a;
    asm("{ .reg .u64 t; cvta.to.shared.u64 t, %1; cvt.u32.u64 %0, t; }"
        : "=r"(a) : "l"(p));
    return a;
}
__device__ __forceinline__ void ldsm4t(uint32_t* r, uint32_t addr) {
    asm volatile("ldmatrix.sync.aligned.m8n8.x4.trans.shared.b16 {%0,%1,%2,%3}, [%4];"
                 : "=r"(r[0]), "=r"(r[1]), "=r"(r[2]), "=r"(r[3]) : "r"(addr));
}
__device__ __forceinline__ void mma_f16(float* d, const uint32_t* a, const uint32_t* b) {
    asm volatile(
        "mma.sync.aligned.m16n8k16.row.col.f32.f16.f16.f32 "
        "{%0,%1,%2,%3}, {%4,%5,%6,%7}, {%8,%9}, {%0,%1,%2,%3};"
        : "+f"(d[0]), "+f"(d[1]), "+f"(d[2]), "+f"(d[3])
        : "r"(a[0]), "r"(a[1]), "r"(a[2]), "r"(a[3]), "r"(b[0]), "r"(b[1]));
}

// ---------------- kernel 1: split-K gram via mma.sync fp16, symmetric-skip ----------------
__global__ void __launch_bounds__(THREADS, 2)
gram_kernel(const float* __restrict__ data, const float* __restrict__ mask,
            const float* __restrict__ mult) {
    __shared__ char Hs[TILE_N * ROWB];       // 17408 B
    __shared__ float mred[KDIM];
    const uint32_t smb = smem_u32(Hs);
    const int tid = threadIdx.x;
    const int wid = tid >> 5;
    const int lane = tid & 31;
    const int chunk = blockIdx.x;
    const int b = blockIdx.y;
    const int n_start = chunk * (CHUNK_TILES * TILE_N);
    const int T = min(CHUNK_TILES, (NTOT - n_start) / TILE_N);

    if (tid < KDIM) mred[tid] = 0.f;

    // convert mapping: thread owns 4 consecutive k, 8 rows (its warp's rows)
    const int kq = (lane) * 4;               // 0..124
    const int rg = wid;                      // warp owns rows rg*8..rg*8+7

    // warp output-tile assignment (upper-triangle coverage):
    //  w0:(0,0,64) w1:(0,64,64) w2:(32,0,64) w3:(32,64,64)
    //  w4:(64,96,32) w5:(64,64,32) w6:(96,96,32) w7:(96,64,32)
    const int i0 = (wid >> 1) * 32;
    const int j0 = (wid < 4) ? (wid & 1) * 64 : 96 - (wid & 1) * 32;
    const int ngw = (wid < 4) ? 4 : 2;       // number of 16-wide j groups

    // ldmatrix lane addressing (validated in rounds 3-4)
    const int grp = lane >> 3, r = lane & 7;
    const uint32_t a_off = (uint32_t)(((grp & 2) ? 8 : 0) + r) * ROWB + (uint32_t)((grp & 1) ? 8 : 0) * 2;
    const uint32_t b_off = (uint32_t)(((grp & 1) ? 8 : 0) + r) * ROWB + (uint32_t)((grp & 2) ? 8 : 0) * 2;

    const float* maskb = mask + (size_t)b * NTOT;
    const float* datab = data + (size_t)b * NTOT;

    float acc[2][4][2][4];
    #pragma unroll
    for (int mt = 0; mt < 2; ++mt)
        #pragma unroll
        for (int g = 0; g < 4; ++g)
            #pragma unroll
            for (int nt = 0; nt < 2; ++nt)
                #pragma unroll
                for (int q = 0; q < 4; ++q) acc[mt][g][nt][q] = 0.f;

    float4 lbuf[8];
    float mbuf[8], dbuf[8];
    float macc[4] = {0.f, 0.f, 0.f, 0.f};

    auto ldg_tile = [&](int t) {
        const int row0 = n_start + t * TILE_N + rg * 8;
        const float* src = mult + (size_t)row0 * KDIM + kq;
        const float* mp = maskb + row0;
        const float* dp = datab + row0;
        #pragma unroll
        for (int i = 0; i < 8; ++i) {
            lbuf[i] = *(const float4*)(src + i * KDIM);
            mbuf[i] = mp[i];
            dbuf[i] = dp[i];
        }
    };

    ldg_tile(0);

    for (int t = 0; t < T; ++t) {
        __syncthreads();     // H free (all warps done MMA of t-1)

        // ---- convert fp32 regs -> fp16 in H, fold rhs ----
        #pragma unroll
        for (int i = 0; i < 8; ++i) {
            const int n = rg * 8 + i;
            const float w = mbuf[i], d = dbuf[i];
            const float x0 = lbuf[i].x * w, x1 = lbuf[i].y * w;
            const float x2 = lbuf[i].z * w, x3 = lbuf[i].w * w;
            macc[0] = fmaf(x0, d, macc[0]);
            macc[1] = fmaf(x1, d, macc[1]);
            macc[2] = fmaf(x2, d, macc[2]);
            macc[3] = fmaf(x3, d, macc[3]);
            uint32_t h01, h23;
            asm("cvt.rn.f16x2.f32 %0, %1, %2;" : "=r"(h01) : "f"(x1), "f"(x0));
            asm("cvt.rn.f16x2.f32 %0, %1, %2;" : "=r"(h23) : "f"(x3), "f"(x2));
            *(uint2*)(Hs + n * ROWB + kq * 2) = make_uint2(h01, h23);
        }
        __syncthreads();     // H ready

        if (t + 1 < T) ldg_tile(t + 1);      // prefetch under MMA latency

        // ---- MMAs: 4 k-steps of 16 over the 64 rows ----
        #pragma unroll
        for (int ks = 0; ks < 4; ++ks) {
            const uint32_t kofs = (uint32_t)ks * 16 * ROWB;
            uint32_t af[2][4];
            ldsm4t(af[0], smb + kofs + a_off + (uint32_t)(i0) * 2);
            ldsm4t(af[1], smb + kofs + a_off + (uint32_t)(i0 + 16) * 2);
            #pragma unroll
            for (int g = 0; g < 4; ++g) {
                if (g < ngw) {
                    uint32_t bh[4];
                    ldsm4t(bh, smb + kofs + b_off + (uint32_t)(j0 + g * 16) * 2);
                    mma_f16(acc[0][g][0], af[0], bh + 0);
                    mma_f16(acc[0][g][1], af[0], bh + 2);
                    mma_f16(acc[1][g][0], af[1], bh + 0);
                    mma_f16(acc[1][g][1], af[1], bh + 2);
                }
            }
        }
    }

    // ---- rhs partial reduce ----
    atomicAdd(&mred[kq],     macc[0]);
    atomicAdd(&mred[kq + 1], macc[1]);
    atomicAdd(&mred[kq + 2], macc[2]);
    atomicAdd(&mred[kq + 3], macc[3]);
    __syncthreads();
    if (tid < KDIM) g_msr[chunk][b][tid] = mred[tid];

    // ---- epilogue: accumulators -> global scratch ----
    const int dg = lane >> 2, dt = (lane & 3) * 2;
    #pragma unroll
    for (int mt = 0; mt < 2; ++mt) {
        #pragma unroll
        for (int g = 0; g < 4; ++g) {
            if (g < ngw) {
                #pragma unroll
                for (int nt = 0; nt < 2; ++nt) {
                    const int i = i0 + mt * 16 + dg;
                    const int j = j0 + g * 16 + nt * 8 + dt;
                    *(float2*)&g_scr[chunk][b][i][j]     = make_float2(acc[mt][g][nt][0], acc[mt][g][nt][1]);
                    *(float2*)&g_scr[chunk][b][i + 8][j] = make_float2(acc[mt][g][nt][2], acc[mt][g][nt][3]);
                }
            }
        }
    }
}

// ---------------- kernel 2: reduce split-K partials + symmetrize ----------------
__global__ void reduce_kernel() {
    const int idx = blockIdx.x * 256 + threadIdx.x;
    const int PER4 = NBATCH * KDIM * KDIM / 4;    // 32768 float4 slots
    if (idx < PER4) {
        const int b = idx >> 12;                  // 4096 float4 per batch
        const int rem = idx & 4095;
        const int i = rem >> 5;
        const int j = (rem & 31) * 4;
        if (i >= 64 && j < 64) return;            // never computed; filled by mirror
        float4 s = make_float4(0.f, 0.f, 0.f, 0.f);
        #pragma unroll
        for (int c = 0; c < NCH; ++c) {
            const float4 v = *(const float4*)&g_scr[c][b][i][j];
            s.x += v.x; s.y += v.y; s.z += v.z; s.w += v.w;
        }
        *(float4*)&g_sa[b][i][j] = s;
        if (i < 64 && j >= 64) {                  // mirror into skipped quadrant
            g_sa[b][j][i]     = s.x;
            g_sa[b][j + 1][i] = s.y;
            g_sa[b][j + 2][i] = s.z;
            g_sa[b][j + 3][i] = s.w;
        }
    } else if (idx < PER4 + NBATCH * KDIM) {
        const int r = idx - PER4;
        const float* p = (const float*)g_msr + r;
        float s = 0.f;
        #pragma unroll
        for (int c = 0; c < NCH; ++c) s += p[c * NBATCH * KDIM];
        ((float*)g_mred)[r] = s;
    }
}

// ---------------- kernel 3: Jacobi solve ----------------
__global__ void solve_kernel(const float* __restrict__ sigma_sq,
                             float* __restrict__ out) {
    __shared__ float xs[2][KDIM];
    __shared__ float mv[KDIM];
    const int b = blockIdx.x;
    const int tid = threadIdx.x;            // 256
    const int i = tid >> 1;
    const int half = tid & 1;
    const int c0 = half * 64;
    const float sig = sigma_sq[0];

    float G[64];
    #pragma unroll 8
    for (int j4 = 0; j4 < 64; j4 += 4) {
        const float4 v = *(const float4*)&g_sa[b][i][c0 + j4];
        G[j4] = v.x; G[j4 + 1] = v.y; G[j4 + 2] = v.z; G[j4 + 3] = v.w;
    }
    #pragma unroll
    for (int q = 0; q < 4; ++q) {
        // add sigma on diagonal (i in this thread's half only)
        if (half == (i >> 6)) { /* diagonal lies in this half */ }
    }
    if (half == (i >> 6)) G[(i & 63)] += sig;
    if (tid < KDIM) mv[tid] = g_mred[b][tid];

    float dval = (half == (i >> 6)) ? G[i & 63] : 0.f;
    dval += __shfl_xor_sync(0xffffffffu, dval, 1);
    const float di = 1.f / dval;
    __syncthreads();
    if (half == 0) xs[0][i] = mv[i] * di;
    __syncthreads();

    for (int it = 0; it < JACOBI_ITERS; ++it) {
        const float* xr = xs[it & 1];
        float* xw = xs[(it & 1) ^ 1];
        float s = 0.f;
        #pragma unroll 16
        for (int j = 0; j < 64; ++j) s = fmaf(G[j], xr[c0 + j], s);
        s += __shfl_xor_sync(0xffffffffu, s, 1);
        if (half == 0) xw[i] = xr[i] + di * (mv[i] - s);
        __syncthreads();
    }
    if (half == 0) out[b * KDIM + i] = xs[0][i];   // even iter count -> buffer 0
}

// ---------------- launch ----------------
extern "C" void kernel_launch(void* const* d_in, const int* in_sizes, int n_in,
                              void* d_out, int out_size) {
    const float* data  = (const float*)d_in[0];
    const float* mask  = (const float*)d_in[1];
    const float* mult  = (const float*)d_in[2];
    const float* sigma = (const float*)d_in[3];
    float* out = (float*)d_out;

    dim3 grid(NCH, NBATCH);
    gram_kernel<<<grid, THREADS>>>(data, mask, mult);

    const int total4 = NBATCH * KDIM * KDIM / 4 + NBATCH * KDIM;
    reduce_kernel<<<(total4 + 255) / 256, 256>>>();

    solve_kernel<<<NBATCH, THREADS>>>(sigma, out);
}

// round 6
// speedup vs baseline: 4.1337x; 1.0230x over previous
#include <cuda_runtime.h>
#include <cstdint>

#define NBATCH 8
#define NTOT   32768
#define KDIM   128
#define NCH    37
#define TILE_N 64
#define CHUNK_TILES 14          // 37*14*64 = 33152 >= 32768; last chunk has 8 tiles
#define JACOBI_ITERS 24
#define THREADS 256

// ---------------- global accumulators (no cudaMalloc allowed) ----------------
__device__ float g_sa[NBATCH][KDIM][KDIM];   // full symmetric gram (atomics)
__device__ float g_mred[NBATCH][KDIM];

// ---------------- smem layout for gram kernel (dynamic) ----------------
#define ROWB   272                     // bytes per H row: 128 f16 (256B) + 16 pad
#define SM_STAGE 0                     // [2][64][128] f32 = 65536
#define SM_H     65536                 // 64 * 272 = 17408
#define SM_MSK   82944                 // [2][64] f32
#define SM_DAT   83456                 // [2][64] f32
#define SM_MRED  83968                 // [128] f32
#define SMEM_TOTAL 84480

// ---------------- helpers ----------------
__device__ __forceinline__ uint32_t smem_u32(const void* p) {
    uint32_t a;
    asm("{ .reg .u64 t; cvta.to.shared.u64 t, %1; cvt.u32.u64 %0, t; }"
        : "=r"(a) : "l"(p));
    return a;
}
__device__ __forceinline__ void cp16(void* s, const void* g) {
    uint32_t a = smem_u32(s);
    asm volatile("cp.async.cg.shared.global [%0], [%1], 16;" :: "r"(a), "l"(g));
}
#define CP_COMMIT() asm volatile("cp.async.commit_group;" ::: "memory")
#define CP_WAIT(n)  asm volatile("cp.async.wait_group %0;" :: "n"(n) : "memory")

__device__ __forceinline__ void ldsm4t(uint32_t* r, uint32_t addr) {
    asm volatile("ldmatrix.sync.aligned.m8n8.x4.trans.shared.b16 {%0,%1,%2,%3}, [%4];"
                 : "=r"(r[0]), "=r"(r[1]), "=r"(r[2]), "=r"(r[3]) : "r"(addr));
}
__device__ __forceinline__ void mma_f16(float* d, const uint32_t* a, const uint32_t* b) {
    asm volatile(
        "mma.sync.aligned.m16n8k16.row.col.f32.f16.f16.f32 "
        "{%0,%1,%2,%3}, {%4,%5,%6,%7}, {%8,%9}, {%0,%1,%2,%3};"
        : "+f"(d[0]), "+f"(d[1]), "+f"(d[2]), "+f"(d[3])
        : "r"(a[0]), "r"(a[1]), "r"(a[2]), "r"(a[3]), "r"(b[0]), "r"(b[1]));
}

// ---------------- kernel 0: zero accumulators ----------------
__global__ void zero_kernel() {
    const int idx = blockIdx.x * 256 + threadIdx.x;
    const int NG = NBATCH * KDIM * KDIM;
    if (idx < NG)                      ((float*)g_sa)[idx] = 0.f;
    else if (idx < NG + NBATCH * KDIM) ((float*)g_mred)[idx - NG] = 0.f;
}

// ---------------- kernel 1: split-K gram, cp.async stage + fp16 MMA + sym skip ----------------
__global__ void __launch_bounds__(THREADS, 2)
gram_kernel(const float* __restrict__ data, const float* __restrict__ mask,
            const float* __restrict__ mult) {
    extern __shared__ char smem[];
    const uint32_t smb = smem_u32(smem);
    const int tid = threadIdx.x;
    const int wid = tid >> 5;
    const int lane = tid & 31;
    const int chunk = blockIdx.x;
    const int b = blockIdx.y;
    const int n_start = chunk * (CHUNK_TILES * TILE_N);
    const int T = min(CHUNK_TILES, (NTOT - n_start) / TILE_N);

    float* stage = (float*)(smem + SM_STAGE);
    float* msk   = (float*)(smem + SM_MSK);
    float* dat   = (float*)(smem + SM_DAT);
    float* mred  = (float*)(smem + SM_MRED);
    const float* maskb = mask + (size_t)b * NTOT;
    const float* datab = data + (size_t)b * NTOT;

    if (tid < KDIM) mred[tid] = 0.f;

    auto prefetch = [&](int tt) {
        const int sb = tt & 1;
        const float* src = mult + (size_t)(n_start + tt * TILE_N) * KDIM;
        float* dst = stage + sb * (TILE_N * KDIM);
        #pragma unroll
        for (int s = 0; s < 8; ++s) {
            const int seg = tid + s * THREADS;         // 0..2047 16B segments
            cp16(dst + seg * 4, src + seg * 4);
        }
        if (tid < 16)      cp16(&msk[sb * 64 + tid * 4],        maskb + n_start + tt * 64 + tid * 4);
        else if (tid < 32) cp16(&dat[sb * 64 + (tid - 16) * 4], datab + n_start + tt * 64 + (tid - 16) * 4);
        CP_COMMIT();
    };

    prefetch(0);

    // conversion mapping: thread owns k-pair k2, 16 n-rows
    const int k2 = (tid & 63) * 2;
    const int ng = tid >> 6;                 // 0..3
    float macc0 = 0.f, macc1 = 0.f;

    // warp output-tile assignment (upper-triangle coverage, SMSP-balanced):
    //  w0:(0,0)x64 w1:(0,64)x64 w2:(32,0)x64 w3:(32,64)x64
    //  w4:(64,96)x32 w5:(64,64)x32 w6:(96,96)x32 w7:(96,64)x32
    const int i0 = (wid >> 1) * 32;
    const int j0 = (wid < 4) ? (wid & 1) * 64 : 96 - (wid & 1) * 32;
    const int ngw = (wid < 4) ? 4 : 2;

    // ldmatrix lane addressing (validated rounds 3-5)
    const int grp = lane >> 3, r = lane & 7;
    const uint32_t a_off = (uint32_t)(((grp & 2) ? 8 : 0) + r) * ROWB + (uint32_t)((grp & 1) ? 8 : 0) * 2;
    const uint32_t b_off = (uint32_t)(((grp & 1) ? 8 : 0) + r) * ROWB + (uint32_t)((grp & 2) ? 8 : 0) * 2;

    float acc[2][4][2][4];
    #pragma unroll
    for (int mt = 0; mt < 2; ++mt)
        #pragma unroll
        for (int g = 0; g < 4; ++g)
            #pragma unroll
            for (int nt = 0; nt < 2; ++nt)
                #pragma unroll
                for (int q = 0; q < 4; ++q) acc[mt][g][nt][q] = 0.f;

    for (int t = 0; t < T; ++t) {
        const int sb = t & 1;
        if (t + 1 < T) { prefetch(t + 1); CP_WAIT(1); }
        else           { CP_WAIT(0); }
        __syncthreads();    // stage[sb] ready; H free (prev MMA done)

        // ---- convert fp32 -> fp16, fold rhs ----
        {
            const float* st = stage + sb * (TILE_N * KDIM);
            const float* mk = msk + sb * 64;
            const float* dd = dat + sb * 64;
            char* hp_base = smem + SM_H;
            #pragma unroll
            for (int i = 0; i < 16; ++i) {
                const int n = ng * 16 + i;
                const float2 v = *(const float2*)&st[n * KDIM + k2];
                const float w = mk[n], d = dd[n];
                const float x0 = v.x * w, x1 = v.y * w;
                macc0 = fmaf(x0, d, macc0);
                macc1 = fmaf(x1, d, macc1);
                uint32_t hp;
                asm("cvt.rn.f16x2.f32 %0, %1, %2;" : "=r"(hp) : "f"(x1), "f"(x0));
                *(uint32_t*)(hp_base + n * ROWB + k2 * 2) = hp;
            }
        }
        __syncthreads();    // H visible to all warps

        // ---- MMAs: 4 k-steps of 16 over the 64 rows ----
        #pragma unroll
        for (int ks = 0; ks < 4; ++ks) {
            const uint32_t kofs = SM_H + (uint32_t)ks * 16 * ROWB;
            uint32_t af[2][4];
            ldsm4t(af[0], smb + kofs + a_off + (uint32_t)(i0) * 2);
            ldsm4t(af[1], smb + kofs + a_off + (uint32_t)(i0 + 16) * 2);
            #pragma unroll
            for (int g = 0; g < 4; ++g) {
                if (g < ngw) {
                    uint32_t bh[4];
                    ldsm4t(bh, smb + kofs + b_off + (uint32_t)(j0 + g * 16) * 2);
                    mma_f16(acc[0][g][0], af[0], bh + 0);
                    mma_f16(acc[0][g][1], af[0], bh + 2);
                    mma_f16(acc[1][g][0], af[1], bh + 0);
                    mma_f16(acc[1][g][1], af[1], bh + 2);
                }
            }
        }
    }

    // ---- rhs partial reduce -> global RED ----
    atomicAdd(&mred[k2], macc0);
    atomicAdd(&mred[k2 + 1], macc1);
    __syncthreads();
    if (tid < KDIM) atomicAdd(&g_mred[b][tid], mred[tid]);

    // ---- epilogue: predicated REDs into g_sa (upper element + mirror) ----
    const int dg = lane >> 2, dt = (lane & 3) * 2;
    #pragma unroll
    for (int mt = 0; mt < 2; ++mt) {
        #pragma unroll
        for (int g = 0; g < 4; ++g) {
            if (g < ngw) {
                #pragma unroll
                for (int nt = 0; nt < 2; ++nt) {
                    #pragma unroll
                    for (int rr = 0; rr < 2; ++rr) {
                        const int i = i0 + mt * 16 + rr * 8 + dg;
                        const int j = j0 + g * 16 + nt * 8 + dt;
                        const float v0 = acc[mt][g][nt][rr * 2];
                        const float v1 = acc[mt][g][nt][rr * 2 + 1];
                        if (j >= i)     atomicAdd(&g_sa[b][i][j], v0);
                        if (j > i)      atomicAdd(&g_sa[b][j][i], v0);
                        if (j + 1 >= i) atomicAdd(&g_sa[b][i][j + 1], v1);
                        if (j + 1 > i)  atomicAdd(&g_sa[b][j + 1][i], v1);
                    }
                }
            }
        }
    }
}

// ---------------- kernel 2: Jacobi solve ----------------
__global__ void solve_kernel(const float* __restrict__ sigma_sq,
                             float* __restrict__ out) {
    __shared__ float xs[2][KDIM];
    __shared__ float mv[KDIM];
    const int b = blockIdx.x;
    const int tid = threadIdx.x;            // 256
    const int i = tid >> 1;
    const int half = tid & 1;
    const int c0 = half * 64;
    const float sig = sigma_sq[0];

    float G[64];
    #pragma unroll 8
    for (int j4 = 0; j4 < 64; j4 += 4) {
        const float4 v = *(const float4*)&g_sa[b][i][c0 + j4];
        G[j4] = v.x; G[j4 + 1] = v.y; G[j4 + 2] = v.z; G[j4 + 3] = v.w;
    }
    if (half == (i >> 6)) G[i & 63] += sig;
    if (tid < KDIM) mv[tid] = g_mred[b][tid];

    float dval = (half == (i >> 6)) ? G[i & 63] : 0.f;
    dval += __shfl_xor_sync(0xffffffffu, dval, 1);
    const float di = 1.f / dval;
    __syncthreads();
    if (half == 0) xs[0][i] = mv[i] * di;
    __syncthreads();

    for (int it = 0; it < JACOBI_ITERS; ++it) {
        const float* xr = xs[it & 1];
        float* xw = xs[(it & 1) ^ 1];
        float s = 0.f;
        #pragma unroll 16
        for (int j = 0; j < 64; ++j) s = fmaf(G[j], xr[c0 + j], s);
        s += __shfl_xor_sync(0xffffffffu, s, 1);
        if (half == 0) xw[i] = xr[i] + di * (mv[i] - s);
        __syncthreads();
    }
    if (half == 0) out[b * KDIM + i] = xs[0][i];   // even iter count -> buffer 0
}

// ---------------- launch ----------------
extern "C" void kernel_launch(void* const* d_in, const int* in_sizes, int n_in,
                              void* d_out, int out_size) {
    const float* data  = (const float*)d_in[0];
    const float* mask  = (const float*)d_in[1];
    const float* mult  = (const float*)d_in[2];
    const float* sigma = (const float*)d_in[3];
    float* out = (float*)d_out;

    cudaFuncSetAttribute(gram_kernel,
                         cudaFuncAttributeMaxDynamicSharedMemorySize, SMEM_TOTAL);

    const int total = NBATCH * KDIM * KDIM + NBATCH * KDIM;
    zero_kernel<<<(total + 255) / 256, 256>>>();

    dim3 grid(NCH, NBATCH);
    gram_kernel<<<grid, THREADS, SMEM_TOTAL>>>(data, mask, mult);

    solve_kernel<<<NBATCH, THREADS>>>(sigma, out);
}